// round 1
// baseline (speedup 1.0000x reference)
#include <cuda_runtime.h>
#include <math.h>

#define DD 256            // head dim (fixed for this problem)
#define MAXN 4096         // B*L
#define MAXV 50304        // vocab padded to multiple of 128

#define MAX_NORM (1.0f - 1e-5f)
#define EPSF 1e-7f

// Scratch (allocation-free rule: __device__ globals)
static __device__ float g_h[(size_t)MAXN * DD];
static __device__ float g_h2[MAXN];
static __device__ float g_v[(size_t)MAXV * DD];
static __device__ float g_v2[MAXV];

// ---------------------------------------------------------------------------
// Projection onto the Poincare ball + squared norm. One row per block,
// 256 threads = 1 element/thread (D = 256).
// ---------------------------------------------------------------------------
template <bool IS_H>
__global__ void proj_kernel(const float* __restrict__ in, int rows) {
    const int row = blockIdx.x;
    const int tid = threadIdx.x;
    if (row >= rows) return;

    float x = in[(size_t)row * DD + tid];
    float p = x * x;
    #pragma unroll
    for (int o = 16; o > 0; o >>= 1) p += __shfl_xor_sync(0xffffffffu, p, o);

    __shared__ float ws[8];
    __shared__ float s_norm2;
    if ((tid & 31) == 0) ws[tid >> 5] = p;
    __syncthreads();
    if (tid == 0) {
        float t = 0.f;
        #pragma unroll
        for (int i = 0; i < 8; i++) t += ws[i];
        s_norm2 = t;
    }
    __syncthreads();

    const float norm2 = s_norm2;
    const float norm = sqrtf(norm2);
    const float scale = (norm > MAX_NORM) ? (MAX_NORM / fmaxf(norm, EPSF)) : 1.0f;
    const float y = x * scale;

    if (IS_H) {
        g_h[(size_t)row * DD + tid] = y;
        if (tid == 0) g_h2[row] = norm2 * scale * scale;
    } else {
        g_v[(size_t)row * DD + tid] = y;
        if (tid == 0) g_v2[row] = norm2 * scale * scale;
    }
}

// ---------------------------------------------------------------------------
// Tiled fp32 GEMM (-2 h.v implicit via epilogue) + fused Poincare distance.
// Block tile 128x128, K-tile 32, 256 threads, 8x8 register tile per thread.
// ---------------------------------------------------------------------------
#define BM 128
#define BN 128
#define BK 32

__global__ __launch_bounds__(256, 2)
void hyp_gemm_kernel(float* __restrict__ out, int N, int V) {
    __shared__ float As[BK][BM + 4];
    __shared__ float Bs[BK][BN + 4];

    const int tid = threadIdx.x;
    const int tx = tid & 15;        // 16 col-groups
    const int ty = tid >> 4;        // 16 row-groups
    const int row0 = blockIdx.y * BM;
    const int col0 = blockIdx.x * BN;

    float acc[8][8];
    #pragma unroll
    for (int i = 0; i < 8; i++)
        #pragma unroll
        for (int j = 0; j < 8; j++) acc[i][j] = 0.f;

    for (int k0 = 0; k0 < DD; k0 += BK) {
        // Cooperative loads: 128 rows x 32 k-floats = 1024 float4, 4 per thread.
        #pragma unroll
        for (int l = 0; l < 4; l++) {
            const int f  = tid + l * 256;   // 0..1023
            const int r  = f >> 3;          // row in tile
            const int c4 = (f & 7) << 2;    // k offset (float4)

            float4 a4 = *reinterpret_cast<const float4*>(
                &g_h[(size_t)(row0 + r) * DD + k0 + c4]);
            As[c4 + 0][r] = a4.x; As[c4 + 1][r] = a4.y;
            As[c4 + 2][r] = a4.z; As[c4 + 3][r] = a4.w;

            const int vr = col0 + r;
            float4 b4 = make_float4(0.f, 0.f, 0.f, 0.f);
            if (vr < V)
                b4 = *reinterpret_cast<const float4*>(
                    &g_v[(size_t)vr * DD + k0 + c4]);
            Bs[c4 + 0][r] = b4.x; Bs[c4 + 1][r] = b4.y;
            Bs[c4 + 2][r] = b4.z; Bs[c4 + 3][r] = b4.w;
        }
        __syncthreads();

        #pragma unroll
        for (int kk = 0; kk < BK; kk++) {
            float a[8], b[8];
            #pragma unroll
            for (int i = 0; i < 8; i++) a[i] = As[kk][ty * 8 + i];
            #pragma unroll
            for (int j = 0; j < 8; j++) b[j] = Bs[kk][tx * 8 + j];
            #pragma unroll
            for (int i = 0; i < 8; i++)
                #pragma unroll
                for (int j = 0; j < 8; j++)
                    acc[i][j] = fmaf(a[i], b[j], acc[i][j]);
        }
        __syncthreads();
    }

    // Fused epilogue: squared euclid -> Poincare distance -> negate.
    float h2l[8], v2l[8];
    #pragma unroll
    for (int i = 0; i < 8; i++) h2l[i] = g_h2[row0 + ty * 8 + i];
    #pragma unroll
    for (int j = 0; j < 8; j++) {
        const int c = col0 + tx * 8 + j;
        v2l[j] = (c < V) ? g_v2[c] : 0.f;
    }

    #pragma unroll
    for (int i = 0; i < 8; i++) {
        const int r = row0 + ty * 8 + i;
        const float h2 = h2l[i];
        const float om_h2 = 1.f - h2;
        #pragma unroll
        for (int j = 0; j < 8; j++) {
            const int c = col0 + tx * 8 + j;
            if (c < V) {
                const float v2 = v2l[j];
                float sq = h2 + v2 - 2.f * acc[i][j];
                sq = fmaxf(sq, 0.f);
                const float denom = fmaxf(om_h2 * (1.f - v2), EPSF);
                float t = (2.f * sq) / denom;
                t = fmaxf(t, 1e-7f);                       // arg clamp 1+1e-7
                // arccosh(1 + t) = log1p(t + sqrt(t*(t+2)))
                const float dist = log1pf(t + sqrtf(t * (t + 2.f)));
                out[(size_t)r * V + c] = -dist;
            }
        }
    }
}

// ---------------------------------------------------------------------------
extern "C" void kernel_launch(void* const* d_in, const int* in_sizes, int n_in,
                              void* d_out, int out_size) {
    const float* hs = (const float*)d_in[0];   // hidden_states [N, 256]
    const float* ve = (const float*)d_in[1];   // vocab_embeddings [V, 256]
    const int N = in_sizes[0] / DD;            // 4096
    const int V = in_sizes[1] / DD;            // 50257

    proj_kernel<true><<<N, 256>>>(hs, N);
    proj_kernel<false><<<V, 256>>>(ve, V);

    dim3 grid((V + BN - 1) / BN, (N + BM - 1) / BM);
    hyp_gemm_kernel<<<grid, 256>>>((float*)d_out, N, V);
}

// round 3
// speedup vs baseline: 2.9874x; 2.9874x over previous
#include <cuda_runtime.h>
#include <cuda_bf16.h>
#include <math.h>
#include <stdint.h>

#define DD 256
#define MAXN 4096
#define MAXV 50432
#define MAX_NORM (1.0f - 1e-5f)
#define EPSF 1e-7f

#define BM 128
#define BN 128
#define BK 32
#define SSTRIDE 40          // bf16 elements per smem row (32 + 8 pad) -> conflict-free ldmatrix

// ---- scratch (__device__ globals: allocation-free rule) ----
static __device__ __nv_bfloat16 g_hb[(size_t)MAXN * DD];
static __device__ __nv_bfloat16 g_vb[(size_t)MAXV * DD];
static __device__ float2 g_h2a[MAXN];   // (h2, 2/(1-h2))
static __device__ float2 g_v2b[MAXV];   // (v2, 1/(1-v2))

// ---------------- PTX helpers ----------------
__device__ __forceinline__ uint32_t smem_u32(const void* p) {
    return (uint32_t)__cvta_generic_to_shared(p);
}
__device__ __forceinline__ void cp16(uint32_t dst, const void* src, bool pred) {
    asm volatile("cp.async.cg.shared.global [%0], [%1], 16, %2;"
                 :: "r"(dst), "l"(src), "r"(pred ? 16u : 0u) : "memory");
}
__device__ __forceinline__ void cp_commit() {
    asm volatile("cp.async.commit_group;" ::: "memory");
}
template <int NN>
__device__ __forceinline__ void cp_wait() {
    asm volatile("cp.async.wait_group %0;" :: "n"(NN) : "memory");
}
__device__ __forceinline__ void ldsm_x4(uint32_t* r, uint32_t addr) {
    asm volatile("ldmatrix.sync.aligned.m8n8.x4.shared.b16 {%0,%1,%2,%3}, [%4];"
                 : "=r"(r[0]), "=r"(r[1]), "=r"(r[2]), "=r"(r[3]) : "r"(addr));
}
__device__ __forceinline__ void mma16816(float* c, const uint32_t* a,
                                         uint32_t b0, uint32_t b1) {
    asm volatile(
        "mma.sync.aligned.m16n8k16.row.col.f32.bf16.bf16.f32 "
        "{%0,%1,%2,%3}, {%4,%5,%6,%7}, {%8,%9}, {%0,%1,%2,%3};"
        : "+f"(c[0]), "+f"(c[1]), "+f"(c[2]), "+f"(c[3])
        : "r"(a[0]), "r"(a[1]), "r"(a[2]), "r"(a[3]), "r"(b0), "r"(b1));
}

// ---------------------------------------------------------------------------
// Projection: warp-per-row. Writes bf16 operand + per-row (n2, recip terms).
// ---------------------------------------------------------------------------
template <bool IS_H>
__global__ void proj_kernel(const float* __restrict__ in, int rows) {
    const int row = blockIdx.x * 8 + (threadIdx.x >> 5);
    const int lane = threadIdx.x & 31;
    if (row >= rows) return;

    const float4* p = reinterpret_cast<const float4*>(in) + (size_t)row * (DD / 4) + lane * 2;
    float4 x0 = p[0], x1 = p[1];
    float s = x0.x * x0.x + x0.y * x0.y + x0.z * x0.z + x0.w * x0.w +
              x1.x * x1.x + x1.y * x1.y + x1.z * x1.z + x1.w * x1.w;
    #pragma unroll
    for (int o = 16; o > 0; o >>= 1) s += __shfl_xor_sync(0xffffffffu, s, o);

    const float norm = sqrtf(s);
    const float scale = (norm > MAX_NORM) ? (MAX_NORM / fmaxf(norm, EPSF)) : 1.0f;
    const float n2 = s * scale * scale;

    __nv_bfloat16 ob[8];
    ob[0] = __float2bfloat16(x0.x * scale); ob[1] = __float2bfloat16(x0.y * scale);
    ob[2] = __float2bfloat16(x0.z * scale); ob[3] = __float2bfloat16(x0.w * scale);
    ob[4] = __float2bfloat16(x1.x * scale); ob[5] = __float2bfloat16(x1.y * scale);
    ob[6] = __float2bfloat16(x1.z * scale); ob[7] = __float2bfloat16(x1.w * scale);

    __nv_bfloat16* dst = (IS_H ? g_hb : g_vb) + (size_t)row * DD + lane * 8;
    *reinterpret_cast<uint4*>(dst) = *reinterpret_cast<const uint4*>(ob);

    if (lane == 0) {
        if (IS_H) g_h2a[row] = make_float2(n2, 2.0f / (1.0f - n2));
        else      g_v2b[row] = make_float2(n2, 1.0f / (1.0f - n2));
    }
}

// ---------------------------------------------------------------------------
// mma.sync bf16 GEMM (128x128 tile, BK=32 double-buffered cp.async) with
// fused Poincare-distance epilogue.
// 8 warps: wm = wid&3 (32 M-rows each), wn = wid>>2 (64 N-cols each).
// Warp tile 32x64 = 2(M) x 8(N) m16n8k16 fragments.
// ---------------------------------------------------------------------------
__global__ void __launch_bounds__(256, 1)
hyp_gemm_kernel(float* __restrict__ out, int N, int V) {
    __shared__ __align__(16) __nv_bfloat16 sA[2][BM * SSTRIDE];
    __shared__ __align__(16) __nv_bfloat16 sB[2][BN * SSTRIDE];

    const int tid = threadIdx.x;
    const int wid = tid >> 5;
    const int lane = tid & 31;
    const int wm = wid & 3;
    const int wn = wid >> 2;
    const int row0 = blockIdx.y * BM;
    const int col0 = blockIdx.x * BN;

    float acc[2][8][4];
    #pragma unroll
    for (int i = 0; i < 2; i++)
        #pragma unroll
        for (int j = 0; j < 8; j++)
            #pragma unroll
            for (int q = 0; q < 4; q++) acc[i][j][q] = 0.f;

    // cooperative load indexing: 512 x 16B chunks per operand per stage
    const int cr = tid >> 2;            // row (0..63) ; two iters -> 128 rows
    const int cc = tid & 3;             // 16B column (0..3)

    const uint32_t sA0 = smem_u32(&sA[0][0]);
    const uint32_t sB0 = smem_u32(&sB[0][0]);
    const uint32_t stageBytesA = BM * SSTRIDE * 2;
    const uint32_t stageBytesB = BN * SSTRIDE * 2;

    auto prefetch = [&](int stage, int k0) {
        #pragma unroll
        for (int i = 0; i < 2; i++) {
            const int r = cr + i * 64;
            const uint32_t so = (uint32_t)(r * SSTRIDE + cc * 8) * 2;
            // A
            cp16(sA0 + stage * stageBytesA + so,
                 &g_hb[(size_t)(row0 + r) * DD + k0 + cc * 8], true);
            // B
            const int vr = col0 + r;
            const bool ok = vr < V;
            cp16(sB0 + stage * stageBytesB + so,
                 &g_vb[(size_t)(ok ? vr : 0) * DD + k0 + cc * 8], ok);
        }
        cp_commit();
    };

    prefetch(0, 0);

    // ldmatrix base offsets (element indices within a stage)
    const int aRowBase = wm * 32 + (lane & 15);
    const int aColSel  = (lane >> 4) * 8;
    const int bRowBase = wn * 64 + (lane & 7) + ((lane >> 4) << 3);
    const int bColSel  = ((lane >> 3) & 1) * 8;

    #pragma unroll 1
    for (int ks = 0; ks < 8; ks++) {
        const int stage = ks & 1;
        if (ks < 7) prefetch(stage ^ 1, (ks + 1) * BK);
        if (ks < 7) cp_wait<1>(); else cp_wait<0>();
        __syncthreads();

        const uint32_t aBase = sA0 + stage * stageBytesA;
        const uint32_t bBase = sB0 + stage * stageBytesB;

        #pragma unroll
        for (int kp = 0; kp < 2; kp++) {
            uint32_t a[2][4];
            #pragma unroll
            for (int mt = 0; mt < 2; mt++) {
                const uint32_t ad = aBase +
                    (uint32_t)((aRowBase + mt * 16) * SSTRIDE + kp * 16 + aColSel) * 2;
                ldsm_x4(a[mt], ad);
            }
            uint32_t b[4][4];
            #pragma unroll
            for (int np = 0; np < 4; np++) {
                const uint32_t bd = bBase +
                    (uint32_t)((bRowBase + np * 16) * SSTRIDE + kp * 16 + bColSel) * 2;
                ldsm_x4(b[np], bd);
            }
            #pragma unroll
            for (int mt = 0; mt < 2; mt++)
                #pragma unroll
                for (int nt = 0; nt < 8; nt++) {
                    const uint32_t b0 = b[nt >> 1][(nt & 1) * 2];
                    const uint32_t b1 = b[nt >> 1][(nt & 1) * 2 + 1];
                    mma16816(acc[mt][nt], a[mt], b0, b1);
                }
        }
        __syncthreads();
    }

    // ---- fused Poincare epilogue ----
    const bool full = (col0 + BN) <= V;
    const int g = lane >> 2;            // 0..7
    const int tg = lane & 3;            // 0..3

    float2 ha[2][2];                    // [mt][rhalf] : (h2, 2/(1-h2))
    #pragma unroll
    for (int mt = 0; mt < 2; mt++) {
        const int r = row0 + wm * 32 + mt * 16 + g;
        ha[mt][0] = g_h2a[r];
        ha[mt][1] = g_h2a[r + 8];
    }

    #pragma unroll
    for (int nt = 0; nt < 8; nt++) {
        const int c = col0 + wn * 64 + nt * 8 + tg * 2;
        float4 vb = make_float4(0.f, 1.f, 0.f, 1.f);
        if (full || c + 1 < V) {
            vb = *reinterpret_cast<const float4*>(&g_v2b[c]);   // 16B aligned (c even)
        } else if (c < V) {
            const float2 t = g_v2b[c];
            vb.x = t.x; vb.y = t.y;
        }
        #pragma unroll
        for (int mt = 0; mt < 2; mt++) {
            #pragma unroll
            for (int rh = 0; rh < 2; rh++) {
                const int r = row0 + wm * 32 + mt * 16 + g + rh * 8;
                const float h2 = ha[mt][rh].x;
                const float a2 = ha[mt][rh].y;
                const float acc0 = acc[mt][nt][rh * 2 + 0];
                const float acc1 = acc[mt][nt][rh * 2 + 1];

                float sq0 = fmaxf(fmaf(-2.0f, acc0, h2 + vb.x), 0.0f);
                float t0 = fmaxf(sq0 * a2 * vb.y, 1e-7f);
                float su0;
                asm("sqrt.approx.f32 %0, %1;" : "=f"(su0) : "f"(t0 * (t0 + 2.0f)));
                float lg0;
                asm("lg2.approx.f32 %0, %1;" : "=f"(lg0) : "f"(1.0f + t0 + su0));

                float sq1 = fmaxf(fmaf(-2.0f, acc1, h2 + vb.z), 0.0f);
                float t1 = fmaxf(sq1 * a2 * vb.w, 1e-7f);
                float su1;
                asm("sqrt.approx.f32 %0, %1;" : "=f"(su1) : "f"(t1 * (t1 + 2.0f)));
                float lg1;
                asm("lg2.approx.f32 %0, %1;" : "=f"(lg1) : "f"(1.0f + t1 + su1));

                float* orow = out + (size_t)r * V;
                if (full) {
                    orow[c]     = lg0 * (-0.6931471805599453f);
                    orow[c + 1] = lg1 * (-0.6931471805599453f);
                } else {
                    if (c < V)     orow[c]     = lg0 * (-0.6931471805599453f);
                    if (c + 1 < V) orow[c + 1] = lg1 * (-0.6931471805599453f);
                }
            }
        }
    }
}

// ---------------------------------------------------------------------------
extern "C" void kernel_launch(void* const* d_in, const int* in_sizes, int n_in,
                              void* d_out, int out_size) {
    const float* hs = (const float*)d_in[0];   // hidden_states [N, 256]
    const float* ve = (const float*)d_in[1];   // vocab_embeddings [V, 256]
    const int N = in_sizes[0] / DD;            // 4096
    const int V = in_sizes[1] / DD;            // 50257

    proj_kernel<true><<<(N + 7) / 8, 256>>>(hs, N);
    proj_kernel<false><<<(V + 7) / 8, 256>>>(ve, V);

    dim3 grid((V + BN - 1) / BN, (N + BM - 1) / BM);
    hyp_gemm_kernel<<<grid, 256>>>((float*)d_out, N, V);
}

// round 5
// speedup vs baseline: 3.7237x; 1.2465x over previous
#include <cuda_runtime.h>
#include <cuda_bf16.h>
#include <math.h>
#include <stdint.h>

#define DD 256
#define MAXN 4096
#define MAXV 50432
#define MAX_NORM (1.0f - 1e-5f)
#define EPSF 1e-7f

#define BM 128
#define BN 128
#define BK 32
#define SSTRIDE 40          // bf16 per smem row (32 + 8 pad) -> conflict-free ldmatrix

// ---- scratch (__device__ globals: allocation-free rule) ----
static __device__ __nv_bfloat16 g_hb[(size_t)MAXN * DD];
static __device__ __nv_bfloat16 g_vb[(size_t)MAXV * DD];
static __device__ float2 g_h2a[MAXN];   // (h2, 2/(1-h2))
static __device__ float2 g_v2b[MAXV];   // (v2, 1/(1-v2))

// ---------------- PTX helpers ----------------
__device__ __forceinline__ uint32_t smem_u32(const void* p) {
    return (uint32_t)__cvta_generic_to_shared(p);
}
__device__ __forceinline__ void cp16(uint32_t dst, const void* src, bool pred) {
    asm volatile("cp.async.cg.shared.global [%0], [%1], 16, %2;"
                 :: "r"(dst), "l"(src), "r"(pred ? 16u : 0u) : "memory");
}
__device__ __forceinline__ void cp_commit() {
    asm volatile("cp.async.commit_group;" ::: "memory");
}
template <int NN>
__device__ __forceinline__ void cp_wait() {
    asm volatile("cp.async.wait_group %0;" :: "n"(NN) : "memory");
}
__device__ __forceinline__ void ldsm_x4(uint32_t* r, uint32_t addr) {
    asm volatile("ldmatrix.sync.aligned.m8n8.x4.shared.b16 {%0,%1,%2,%3}, [%4];"
                 : "=r"(r[0]), "=r"(r[1]), "=r"(r[2]), "=r"(r[3]) : "r"(addr));
}
__device__ __forceinline__ void mma16816(float* c, const uint32_t* a,
                                         uint32_t b0, uint32_t b1) {
    asm volatile(
        "mma.sync.aligned.m16n8k16.row.col.f32.bf16.bf16.f32 "
        "{%0,%1,%2,%3}, {%4,%5,%6,%7}, {%8,%9}, {%0,%1,%2,%3};"
        : "+f"(c[0]), "+f"(c[1]), "+f"(c[2]), "+f"(c[3])
        : "r"(a[0]), "r"(a[1]), "r"(a[2]), "r"(a[3]), "r"(b0), "r"(b1));
}
__device__ __forceinline__ void stcs1(float* p, float x) {
    asm volatile("st.global.cs.f32 [%0], %1;" :: "l"(p), "f"(x) : "memory");
}

// ---------------------------------------------------------------------------
// Projection: warp-per-row. Writes bf16 operand + per-row (n2, recip terms).
// ---------------------------------------------------------------------------
template <bool IS_H>
__global__ void proj_kernel(const float* __restrict__ in, int rows) {
    const int row = blockIdx.x * 8 + (threadIdx.x >> 5);
    const int lane = threadIdx.x & 31;
    if (row >= rows) return;

    const float4* p = reinterpret_cast<const float4*>(in) + (size_t)row * (DD / 4) + lane * 2;
    float4 x0 = p[0], x1 = p[1];
    float s = x0.x * x0.x + x0.y * x0.y + x0.z * x0.z + x0.w * x0.w +
              x1.x * x1.x + x1.y * x1.y + x1.z * x1.z + x1.w * x1.w;
    #pragma unroll
    for (int o = 16; o > 0; o >>= 1) s += __shfl_xor_sync(0xffffffffu, s, o);

    const float norm = sqrtf(s);
    const float scale = (norm > MAX_NORM) ? (MAX_NORM / fmaxf(norm, EPSF)) : 1.0f;
    const float n2 = s * scale * scale;

    __nv_bfloat16 ob[8];
    ob[0] = __float2bfloat16(x0.x * scale); ob[1] = __float2bfloat16(x0.y * scale);
    ob[2] = __float2bfloat16(x0.z * scale); ob[3] = __float2bfloat16(x0.w * scale);
    ob[4] = __float2bfloat16(x1.x * scale); ob[5] = __float2bfloat16(x1.y * scale);
    ob[6] = __float2bfloat16(x1.z * scale); ob[7] = __float2bfloat16(x1.w * scale);

    __nv_bfloat16* dst = (IS_H ? g_hb : g_vb) + (size_t)row * DD + lane * 8;
    *reinterpret_cast<uint4*>(dst) = *reinterpret_cast<const uint4*>(ob);

    if (lane == 0) {
        if (IS_H) g_h2a[row] = make_float2(n2, 2.0f / (1.0f - n2));
        else      g_v2b[row] = make_float2(n2, 1.0f / (1.0f - n2));
    }
}

// ---------------------------------------------------------------------------
// mma.sync bf16 GEMM (128x128 tile, BK=32 double-buffered cp.async) with
// fused Poincare-distance epilogue. 2 CTAs/SM.
// 8 warps: wm = wid&3 (32 M-rows each), wn = wid>>2 (64 N-cols each).
// ---------------------------------------------------------------------------
__global__ void __launch_bounds__(256, 2)
hyp_gemm_kernel(float* __restrict__ out, int N, int V) {
    __shared__ __align__(16) __nv_bfloat16 sA[2][BM * SSTRIDE];
    __shared__ __align__(16) __nv_bfloat16 sB[2][BN * SSTRIDE];

    const int tid = threadIdx.x;
    const int wid = tid >> 5;
    const int lane = tid & 31;
    const int wm = wid & 3;
    const int wn = wid >> 2;
    const int row0 = blockIdx.y * BM;
    const int col0 = blockIdx.x * BN;

    float acc[2][8][4];
    #pragma unroll
    for (int i = 0; i < 2; i++)
        #pragma unroll
        for (int j = 0; j < 8; j++)
            #pragma unroll
            for (int q = 0; q < 4; q++) acc[i][j][q] = 0.f;

    const int cr = tid >> 2;            // row (0..63); two iters -> 128 rows
    const int cc = tid & 3;             // 16B column

    const uint32_t sA0 = smem_u32(&sA[0][0]);
    const uint32_t sB0 = smem_u32(&sB[0][0]);
    const uint32_t stageBytes = BM * SSTRIDE * 2;

    auto prefetch = [&](int stage, int k0) {
        #pragma unroll
        for (int i = 0; i < 2; i++) {
            const int r = cr + i * 64;
            const uint32_t so = (uint32_t)(r * SSTRIDE + cc * 8) * 2;
            cp16(sA0 + stage * stageBytes + so,
                 &g_hb[(size_t)(row0 + r) * DD + k0 + cc * 8], true);
            const int vr = col0 + r;
            const bool ok = vr < V;
            cp16(sB0 + stage * stageBytes + so,
                 &g_vb[(size_t)(ok ? vr : 0) * DD + k0 + cc * 8], ok);
        }
        cp_commit();
    };

    prefetch(0, 0);

    const int aRowBase = wm * 32 + (lane & 15);
    const int aColSel  = (lane >> 4) * 8;
    const int bRowBase = wn * 64 + (lane & 7) + ((lane >> 4) << 3);
    const int bColSel  = ((lane >> 3) & 1) * 8;

    // One __syncthreads per k-iter: after the sync every warp has finished
    // reading stage^1 (used in the previous iter), so prefetching into it
    // while computing on `stage` is race-free.
    #pragma unroll 1
    for (int ks = 0; ks < 8; ks++) {
        const int stage = ks & 1;
        cp_wait<0>();
        __syncthreads();
        if (ks < 7) prefetch(stage ^ 1, (ks + 1) * BK);

        const uint32_t aBase = sA0 + stage * stageBytes;
        const uint32_t bBase = sB0 + stage * stageBytes;

        #pragma unroll
        for (int kp = 0; kp < 2; kp++) {
            uint32_t a[2][4];
            #pragma unroll
            for (int mt = 0; mt < 2; mt++) {
                const uint32_t ad = aBase +
                    (uint32_t)((aRowBase + mt * 16) * SSTRIDE + kp * 16 + aColSel) * 2;
                ldsm_x4(a[mt], ad);
            }
            uint32_t b[4][4];
            #pragma unroll
            for (int np = 0; np < 4; np++) {
                const uint32_t bd = bBase +
                    (uint32_t)((bRowBase + np * 16) * SSTRIDE + kp * 16 + bColSel) * 2;
                ldsm_x4(b[np], bd);
            }
            #pragma unroll
            for (int mt = 0; mt < 2; mt++)
                #pragma unroll
                for (int nt = 0; nt < 8; nt++)
                    mma16816(acc[mt][nt], a[mt],
                             b[nt >> 1][(nt & 1) * 2], b[nt >> 1][(nt & 1) * 2 + 1]);
        }
    }

    // ---- fused Poincare epilogue (streaming scalar stores; V odd -> no v2) ----
    const bool full = (col0 + BN) <= V;
    const int g = lane >> 2;
    const int tg = lane & 3;

    float2 ha[2][2];
    #pragma unroll
    for (int mt = 0; mt < 2; mt++) {
        const int r = row0 + wm * 32 + mt * 16 + g;
        ha[mt][0] = g_h2a[r];
        ha[mt][1] = g_h2a[r + 8];
    }

    #pragma unroll
    for (int nt = 0; nt < 8; nt++) {
        const int c = col0 + wn * 64 + nt * 8 + tg * 2;
        float4 vb = make_float4(0.f, 1.f, 0.f, 1.f);
        if (full || c + 1 < V) {
            vb = *reinterpret_cast<const float4*>(&g_v2b[c]);
        } else if (c < V) {
            const float2 t = g_v2b[c];
            vb.x = t.x; vb.y = t.y;
        }
        #pragma unroll
        for (int mt = 0; mt < 2; mt++) {
            #pragma unroll
            for (int rh = 0; rh < 2; rh++) {
                const int r = row0 + wm * 32 + mt * 16 + g + rh * 8;
                const float h2 = ha[mt][rh].x;
                const float a2 = ha[mt][rh].y;
                const float acc0 = acc[mt][nt][rh * 2 + 0];
                const float acc1 = acc[mt][nt][rh * 2 + 1];

                float sq0 = fmaxf(fmaf(-2.0f, acc0, h2 + vb.x), 0.0f);
                float t0 = fmaxf(sq0 * a2 * vb.y, 1e-7f);
                float su0;
                asm("sqrt.approx.f32 %0, %1;" : "=f"(su0) : "f"(t0 * (t0 + 2.0f)));
                float lg0;
                asm("lg2.approx.f32 %0, %1;" : "=f"(lg0) : "f"(1.0f + t0 + su0));

                float sq1 = fmaxf(fmaf(-2.0f, acc1, h2 + vb.z), 0.0f);
                float t1 = fmaxf(sq1 * a2 * vb.w, 1e-7f);
                float su1;
                asm("sqrt.approx.f32 %0, %1;" : "=f"(su1) : "f"(t1 * (t1 + 2.0f)));
                float lg1;
                asm("lg2.approx.f32 %0, %1;" : "=f"(lg1) : "f"(1.0f + t1 + su1));

                float* orow = out + (size_t)r * V;
                const float o0 = lg0 * (-0.6931471805599453f);
                const float o1 = lg1 * (-0.6931471805599453f);
                if (full) {
                    stcs1(&orow[c], o0);
                    stcs1(&orow[c + 1], o1);
                } else {
                    if (c < V)     stcs1(&orow[c], o0);
                    if (c + 1 < V) stcs1(&orow[c + 1], o1);
                }
            }
        }
    }
}

// ---------------------------------------------------------------------------
extern "C" void kernel_launch(void* const* d_in, const int* in_sizes, int n_in,
                              void* d_out, int out_size) {
    const float* hs = (const float*)d_in[0];   // hidden_states [N, 256]
    const float* ve = (const float*)d_in[1];   // vocab_embeddings [V, 256]
    const int N = in_sizes[0] / DD;            // 4096
    const int V = in_sizes[1] / DD;            // 50257

    proj_kernel<true><<<(N + 7) / 8, 256>>>(hs, N);
    proj_kernel<false><<<(V + 7) / 8, 256>>>(ve, V);

    dim3 grid((V + BN - 1) / BN, (N + BM - 1) / BM);
    hyp_gemm_kernel<<<grid, 256>>>((float*)d_out, N, V);
}

// round 6
// speedup vs baseline: 4.2234x; 1.1342x over previous
#include <cuda_runtime.h>
#include <cuda_bf16.h>
#include <math.h>
#include <stdint.h>

#define DD 256
#define MAXN 4096
#define MAXV 50432
#define MAX_NORM (1.0f - 1e-5f)
#define EPSF 1e-7f

#define BM 128
#define BN 128
#define BK 64
#define SSTRIDE 72          // bf16 per smem row (64 + 8 pad) -> conflict-free ldmatrix

#define STAGE_BYTES (BM * SSTRIDE * 2)        // 18432 B per operand per stage
#define SMEM_TOTAL  (4 * STAGE_BYTES)         // A0,A1,B0,B1 = 73728 B

// ---- scratch (__device__ globals: allocation-free rule) ----
static __device__ __nv_bfloat16 g_hb[(size_t)MAXN * DD];
static __device__ __nv_bfloat16 g_vb[(size_t)MAXV * DD];
static __device__ float2 g_h2a[MAXN];   // (h2, 2/(1-h2))
static __device__ float2 g_v2b[MAXV];   // (v2, 1/(1-v2))

// ---------------- PTX helpers ----------------
__device__ __forceinline__ uint32_t smem_u32(const void* p) {
    return (uint32_t)__cvta_generic_to_shared(p);
}
__device__ __forceinline__ void cp16(uint32_t dst, const void* src, bool pred) {
    asm volatile("cp.async.cg.shared.global [%0], [%1], 16, %2;"
                 :: "r"(dst), "l"(src), "r"(pred ? 16u : 0u) : "memory");
}
__device__ __forceinline__ void cp_commit() {
    asm volatile("cp.async.commit_group;" ::: "memory");
}
template <int NN>
__device__ __forceinline__ void cp_wait() {
    asm volatile("cp.async.wait_group %0;" :: "n"(NN) : "memory");
}
__device__ __forceinline__ void ldsm_x4(uint32_t* r, uint32_t addr) {
    asm volatile("ldmatrix.sync.aligned.m8n8.x4.shared.b16 {%0,%1,%2,%3}, [%4];"
                 : "=r"(r[0]), "=r"(r[1]), "=r"(r[2]), "=r"(r[3]) : "r"(addr));
}
__device__ __forceinline__ void mma16816(float* c, const uint32_t* a,
                                         uint32_t b0, uint32_t b1) {
    asm volatile(
        "mma.sync.aligned.m16n8k16.row.col.f32.bf16.bf16.f32 "
        "{%0,%1,%2,%3}, {%4,%5,%6,%7}, {%8,%9}, {%0,%1,%2,%3};"
        : "+f"(c[0]), "+f"(c[1]), "+f"(c[2]), "+f"(c[3])
        : "r"(a[0]), "r"(a[1]), "r"(a[2]), "r"(a[3]), "r"(b0), "r"(b1));
}
__device__ __forceinline__ void stcs1(float* p, float x) {
    asm volatile("st.global.cs.f32 [%0], %1;" :: "l"(p), "f"(x) : "memory");
}

// ---------------------------------------------------------------------------
// Projection: warp-per-row. Writes bf16 operand + per-row (n2, recip terms).
// ---------------------------------------------------------------------------
template <bool IS_H>
__global__ void proj_kernel(const float* __restrict__ in, int rows) {
    const int row = blockIdx.x * 8 + (threadIdx.x >> 5);
    const int lane = threadIdx.x & 31;
    if (row >= rows) return;

    const float4* p = reinterpret_cast<const float4*>(in) + (size_t)row * (DD / 4) + lane * 2;
    float4 x0 = p[0], x1 = p[1];
    float s = x0.x * x0.x + x0.y * x0.y + x0.z * x0.z + x0.w * x0.w +
              x1.x * x1.x + x1.y * x1.y + x1.z * x1.z + x1.w * x1.w;
    #pragma unroll
    for (int o = 16; o > 0; o >>= 1) s += __shfl_xor_sync(0xffffffffu, s, o);

    const float norm = sqrtf(s);
    const float scale = (norm > MAX_NORM) ? (MAX_NORM / fmaxf(norm, EPSF)) : 1.0f;
    const float n2 = s * scale * scale;

    __nv_bfloat16 ob[8];
    ob[0] = __float2bfloat16(x0.x * scale); ob[1] = __float2bfloat16(x0.y * scale);
    ob[2] = __float2bfloat16(x0.z * scale); ob[3] = __float2bfloat16(x0.w * scale);
    ob[4] = __float2bfloat16(x1.x * scale); ob[5] = __float2bfloat16(x1.y * scale);
    ob[6] = __float2bfloat16(x1.z * scale); ob[7] = __float2bfloat16(x1.w * scale);

    __nv_bfloat16* dst = (IS_H ? g_hb : g_vb) + (size_t)row * DD + lane * 8;
    *reinterpret_cast<uint4*>(dst) = *reinterpret_cast<const uint4*>(ob);

    if (lane == 0) {
        if (IS_H) g_h2a[row] = make_float2(n2, 2.0f / (1.0f - n2));
        else      g_v2b[row] = make_float2(n2, 1.0f / (1.0f - n2));
    }
}

// ---------------------------------------------------------------------------
// mma.sync bf16 GEMM (128x128 tile, BK=64 double-buffered cp.async, 4 k-iters)
// with fused Poincare-distance epilogue. 2 CTAs/SM (dynamic smem 72KB/CTA).
// 8 warps: wm = wid&3 (32 M-rows each), wn = wid>>2 (64 N-cols each).
// ---------------------------------------------------------------------------
__global__ void __launch_bounds__(256, 2)
hyp_gemm_kernel(float* __restrict__ out, int N, int V) {
    extern __shared__ __align__(16) char smem[];
    // layout: A stage0 | A stage1 | B stage0 | B stage1
    const uint32_t sA0 = smem_u32(smem);
    const uint32_t sB0 = sA0 + 2 * STAGE_BYTES;

    const int tid = threadIdx.x;
    const int wid = tid >> 5;
    const int lane = tid & 31;
    const int wm = wid & 3;
    const int wn = wid >> 2;
    const int row0 = blockIdx.y * BM;
    const int col0 = blockIdx.x * BN;

    float acc[2][8][4];
    #pragma unroll
    for (int i = 0; i < 2; i++)
        #pragma unroll
        for (int j = 0; j < 8; j++)
            #pragma unroll
            for (int q = 0; q < 4; q++) acc[i][j][q] = 0.f;

    // cooperative load: 128 rows x 128B (8 x 16B) per operand per stage
    const int cr = tid >> 3;            // 0..31, x4 iters -> 128 rows
    const int cc = tid & 7;             // 16B column 0..7

    auto prefetch = [&](int stage, int k0) {
        #pragma unroll
        for (int i = 0; i < 4; i++) {
            const int r = cr + i * 32;
            const uint32_t so = (uint32_t)(r * SSTRIDE + cc * 8) * 2;
            cp16(sA0 + stage * STAGE_BYTES + so,
                 &g_hb[(size_t)(row0 + r) * DD + k0 + cc * 8], true);
            const int vr = col0 + r;
            const bool ok = vr < V;
            cp16(sB0 + stage * STAGE_BYTES + so,
                 &g_vb[(size_t)(ok ? vr : 0) * DD + k0 + cc * 8], ok);
        }
        cp_commit();
    };

    prefetch(0, 0);

    const int aRowBase = wm * 32 + (lane & 15);
    const int aColSel  = (lane >> 4) * 8;
    const int bRowBase = wn * 64 + (lane & 7) + ((lane >> 4) << 3);
    const int bColSel  = ((lane >> 3) & 1) * 8;

    #pragma unroll 1
    for (int ks = 0; ks < 4; ks++) {
        const int stage = ks & 1;
        cp_wait<0>();
        __syncthreads();
        if (ks < 3) prefetch(stage ^ 1, (ks + 1) * BK);

        const uint32_t aBase = sA0 + stage * STAGE_BYTES;
        const uint32_t bBase = sB0 + stage * STAGE_BYTES;

        #pragma unroll
        for (int kp = 0; kp < 4; kp++) {
            uint32_t a[2][4];
            #pragma unroll
            for (int mt = 0; mt < 2; mt++) {
                const uint32_t ad = aBase +
                    (uint32_t)((aRowBase + mt * 16) * SSTRIDE + kp * 16 + aColSel) * 2;
                ldsm_x4(a[mt], ad);
            }
            uint32_t b[4][4];
            #pragma unroll
            for (int np = 0; np < 4; np++) {
                const uint32_t bd = bBase +
                    (uint32_t)((bRowBase + np * 16) * SSTRIDE + kp * 16 + bColSel) * 2;
                ldsm_x4(b[np], bd);
            }
            #pragma unroll
            for (int mt = 0; mt < 2; mt++)
                #pragma unroll
                for (int nt = 0; nt < 8; nt++)
                    mma16816(acc[mt][nt], a[mt],
                             b[nt >> 1][(nt & 1) * 2], b[nt >> 1][(nt & 1) * 2 + 1]);
        }
    }

    // ---- fused Poincare epilogue (streaming scalar stores; V odd -> no v2) ----
    const bool full = (col0 + BN) <= V;
    const int g = lane >> 2;
    const int tg = lane & 3;

    float2 ha[2][2];
    #pragma unroll
    for (int mt = 0; mt < 2; mt++) {
        const int r = row0 + wm * 32 + mt * 16 + g;
        ha[mt][0] = g_h2a[r];
        ha[mt][1] = g_h2a[r + 8];
    }

    #pragma unroll
    for (int nt = 0; nt < 8; nt++) {
        const int c = col0 + wn * 64 + nt * 8 + tg * 2;
        float4 vb = make_float4(0.f, 1.f, 0.f, 1.f);
        if (full || c + 1 < V) {
            vb = *reinterpret_cast<const float4*>(&g_v2b[c]);
        } else if (c < V) {
            const float2 t = g_v2b[c];
            vb.x = t.x; vb.y = t.y;
        }
        #pragma unroll
        for (int mt = 0; mt < 2; mt++) {
            #pragma unroll
            for (int rh = 0; rh < 2; rh++) {
                const int r = row0 + wm * 32 + mt * 16 + g + rh * 8;
                const float h2 = ha[mt][rh].x;
                const float a2 = ha[mt][rh].y;
                const float acc0 = acc[mt][nt][rh * 2 + 0];
                const float acc1 = acc[mt][nt][rh * 2 + 1];

                float sq0 = fmaxf(fmaf(-2.0f, acc0, h2 + vb.x), 0.0f);
                float t0 = fmaxf(sq0 * a2 * vb.y, 1e-7f);
                float su0;
                asm("sqrt.approx.f32 %0, %1;" : "=f"(su0) : "f"(t0 * (t0 + 2.0f)));
                float lg0;
                asm("lg2.approx.f32 %0, %1;" : "=f"(lg0) : "f"(1.0f + t0 + su0));

                float sq1 = fmaxf(fmaf(-2.0f, acc1, h2 + vb.z), 0.0f);
                float t1 = fmaxf(sq1 * a2 * vb.w, 1e-7f);
                float su1;
                asm("sqrt.approx.f32 %0, %1;" : "=f"(su1) : "f"(t1 * (t1 + 2.0f)));
                float lg1;
                asm("lg2.approx.f32 %0, %1;" : "=f"(lg1) : "f"(1.0f + t1 + su1));

                float* orow = out + (size_t)r * V;
                const float o0 = lg0 * (-0.6931471805599453f);
                const float o1 = lg1 * (-0.6931471805599453f);
                if (full) {
                    stcs1(&orow[c], o0);
                    stcs1(&orow[c + 1], o1);
                } else {
                    if (c < V)     stcs1(&orow[c], o0);
                    if (c + 1 < V) stcs1(&orow[c + 1], o1);
                }
            }
        }
    }
}

// ---------------------------------------------------------------------------
extern "C" void kernel_launch(void* const* d_in, const int* in_sizes, int n_in,
                              void* d_out, int out_size) {
    const float* hs = (const float*)d_in[0];   // hidden_states [N, 256]
    const float* ve = (const float*)d_in[1];   // vocab_embeddings [V, 256]
    const int N = in_sizes[0] / DD;            // 4096
    const int V = in_sizes[1] / DD;            // 50257

    proj_kernel<true><<<(N + 7) / 8, 256>>>(hs, N);
    proj_kernel<false><<<(V + 7) / 8, 256>>>(ve, V);

    static int smem_set = 0;
    if (!smem_set) {
        cudaFuncSetAttribute(hyp_gemm_kernel,
                             cudaFuncAttributeMaxDynamicSharedMemorySize, SMEM_TOTAL);
        smem_set = 1;
    }
    dim3 grid((V + BN - 1) / BN, (N + BM - 1) / BM);
    hyp_gemm_kernel<<<grid, 256, SMEM_TOTAL>>>((float*)d_out, N, V);
}

// round 7
// speedup vs baseline: 5.6493x; 1.3376x over previous
#include <cuda_runtime.h>
#include <cuda_bf16.h>
#include <math.h>
#include <stdint.h>

#define DD 256
#define MAXN 4096
#define MAXV 50432
#define MAX_NORM (1.0f - 1e-5f)
#define EPSF 1e-7f

#define BM 128
#define BN 128
#define BK 64
#define SSTRIDE 72          // bf16 per smem row (64 + 8 pad) -> conflict-free ldmatrix

#define STAGE_BYTES (BM * SSTRIDE * 2)        // 18432 B per operand per stage
#define CSTRIDE 132                            // fp32 epilogue tile stride
#define SMEM_TOTAL  (4 * STAGE_BYTES)         // 73728 B (>= 128*132*4 + 128*8)

// ---- scratch (__device__ globals: allocation-free rule) ----
static __device__ __nv_bfloat16 g_hb[(size_t)MAXN * DD];
static __device__ __nv_bfloat16 g_vb[(size_t)MAXV * DD];
static __device__ float2 g_h2a[MAXN];   // (h2, 2/(1-h2))
static __device__ float2 g_v2b[MAXV];   // (v2, 1/(1-v2))

// ---------------- PTX helpers ----------------
__device__ __forceinline__ uint32_t smem_u32(const void* p) {
    return (uint32_t)__cvta_generic_to_shared(p);
}
__device__ __forceinline__ void cp16(uint32_t dst, const void* src, bool pred) {
    asm volatile("cp.async.cg.shared.global [%0], [%1], 16, %2;"
                 :: "r"(dst), "l"(src), "r"(pred ? 16u : 0u) : "memory");
}
__device__ __forceinline__ void cp_commit() {
    asm volatile("cp.async.commit_group;" ::: "memory");
}
template <int NN>
__device__ __forceinline__ void cp_wait() {
    asm volatile("cp.async.wait_group %0;" :: "n"(NN) : "memory");
}
__device__ __forceinline__ void ldsm_x4(uint32_t* r, uint32_t addr) {
    asm volatile("ldmatrix.sync.aligned.m8n8.x4.shared.b16 {%0,%1,%2,%3}, [%4];"
                 : "=r"(r[0]), "=r"(r[1]), "=r"(r[2]), "=r"(r[3]) : "r"(addr));
}
__device__ __forceinline__ void mma16816(float* c, const uint32_t* a,
                                         uint32_t b0, uint32_t b1) {
    asm volatile(
        "mma.sync.aligned.m16n8k16.row.col.f32.bf16.bf16.f32 "
        "{%0,%1,%2,%3}, {%4,%5,%6,%7}, {%8,%9}, {%0,%1,%2,%3};"
        : "+f"(c[0]), "+f"(c[1]), "+f"(c[2]), "+f"(c[3])
        : "r"(a[0]), "r"(a[1]), "r"(a[2]), "r"(a[3]), "r"(b0), "r"(b1));
}
__device__ __forceinline__ void stcs1(float* p, float x) {
    asm volatile("st.global.cs.f32 [%0], %1;" :: "l"(p), "f"(x) : "memory");
}

// ---------------------------------------------------------------------------
// Projection: warp-per-row. Writes bf16 operand + per-row (n2, recip terms).
// ---------------------------------------------------------------------------
template <bool IS_H>
__global__ void proj_kernel(const float* __restrict__ in, int rows) {
    const int row = blockIdx.x * 8 + (threadIdx.x >> 5);
    const int lane = threadIdx.x & 31;
    if (row >= rows) return;

    const float4* p = reinterpret_cast<const float4*>(in) + (size_t)row * (DD / 4) + lane * 2;
    float4 x0 = p[0], x1 = p[1];
    float s = x0.x * x0.x + x0.y * x0.y + x0.z * x0.z + x0.w * x0.w +
              x1.x * x1.x + x1.y * x1.y + x1.z * x1.z + x1.w * x1.w;
    #pragma unroll
    for (int o = 16; o > 0; o >>= 1) s += __shfl_xor_sync(0xffffffffu, s, o);

    const float norm = sqrtf(s);
    const float scale = (norm > MAX_NORM) ? (MAX_NORM / fmaxf(norm, EPSF)) : 1.0f;
    const float n2 = s * scale * scale;

    __nv_bfloat16 ob[8];
    ob[0] = __float2bfloat16(x0.x * scale); ob[1] = __float2bfloat16(x0.y * scale);
    ob[2] = __float2bfloat16(x0.z * scale); ob[3] = __float2bfloat16(x0.w * scale);
    ob[4] = __float2bfloat16(x1.x * scale); ob[5] = __float2bfloat16(x1.y * scale);
    ob[6] = __float2bfloat16(x1.z * scale); ob[7] = __float2bfloat16(x1.w * scale);

    __nv_bfloat16* dst = (IS_H ? g_hb : g_vb) + (size_t)row * DD + lane * 8;
    *reinterpret_cast<uint4*>(dst) = *reinterpret_cast<const uint4*>(ob);

    if (lane == 0) {
        if (IS_H) g_h2a[row] = make_float2(n2, 2.0f / (1.0f - n2));
        else      g_v2b[row] = make_float2(n2, 1.0f / (1.0f - n2));
    }
}

// ---------------------------------------------------------------------------
// mma.sync bf16 GEMM (128x128 tile, BK=64 double-buffered, 4 k-iters) with
// smem-staged, fully-coalesced Poincare epilogue. 2 CTAs/SM.
// ---------------------------------------------------------------------------
__global__ void __launch_bounds__(256, 2)
hyp_gemm_kernel(float* __restrict__ out, int N, int V) {
    extern __shared__ __align__(16) char smem[];
    const uint32_t sA0 = smem_u32(smem);
    const uint32_t sB0 = sA0 + 2 * STAGE_BYTES;

    const int tid = threadIdx.x;
    const int wid = tid >> 5;
    const int lane = tid & 31;
    const int wm = wid & 3;
    const int wn = wid >> 2;
    const int row0 = blockIdx.y * BM;
    const int col0 = blockIdx.x * BN;

    float acc[2][8][4];
    #pragma unroll
    for (int i = 0; i < 2; i++)
        #pragma unroll
        for (int j = 0; j < 8; j++)
            #pragma unroll
            for (int q = 0; q < 4; q++) acc[i][j][q] = 0.f;

    const int cr = tid >> 3;            // 0..31, x4 iters -> 128 rows
    const int cc = tid & 7;             // 16B column 0..7

    auto prefetch = [&](int stage, int k0) {
        #pragma unroll
        for (int i = 0; i < 4; i++) {
            const int r = cr + i * 32;
            const uint32_t so = (uint32_t)(r * SSTRIDE + cc * 8) * 2;
            cp16(sA0 + stage * STAGE_BYTES + so,
                 &g_hb[(size_t)(row0 + r) * DD + k0 + cc * 8], true);
            const int vr = col0 + r;
            const bool ok = vr < V;
            cp16(sB0 + stage * STAGE_BYTES + so,
                 &g_vb[(size_t)(ok ? vr : 0) * DD + k0 + cc * 8], ok);
        }
        cp_commit();
    };

    prefetch(0, 0);

    const int aRowBase = wm * 32 + (lane & 15);
    const int aColSel  = (lane >> 4) * 8;
    const int bRowBase = wn * 64 + (lane & 7) + ((lane >> 4) << 3);
    const int bColSel  = ((lane >> 3) & 1) * 8;

    #pragma unroll 1
    for (int ks = 0; ks < 4; ks++) {
        const int stage = ks & 1;
        cp_wait<0>();
        __syncthreads();
        if (ks < 3) prefetch(stage ^ 1, (ks + 1) * BK);

        const uint32_t aBase = sA0 + stage * STAGE_BYTES;
        const uint32_t bBase = sB0 + stage * STAGE_BYTES;

        #pragma unroll
        for (int kp = 0; kp < 4; kp++) {
            uint32_t a[2][4];
            #pragma unroll
            for (int mt = 0; mt < 2; mt++) {
                const uint32_t ad = aBase +
                    (uint32_t)((aRowBase + mt * 16) * SSTRIDE + kp * 16 + aColSel) * 2;
                ldsm_x4(a[mt], ad);
            }
            uint32_t b[4][4];
            #pragma unroll
            for (int np = 0; np < 4; np++) {
                const uint32_t bd = bBase +
                    (uint32_t)((bRowBase + np * 16) * SSTRIDE + kp * 16 + bColSel) * 2;
                ldsm_x4(b[np], bd);
            }
            #pragma unroll
            for (int mt = 0; mt < 2; mt++)
                #pragma unroll
                for (int nt = 0; nt < 8; nt++)
                    mma16816(acc[mt][nt], a[mt],
                             b[nt >> 1][(nt & 1) * 2], b[nt >> 1][(nt & 1) * 2 + 1]);
        }
    }

    // ---- stage accumulators (and h2a) into smem ----
    cp_wait<0>();
    __syncthreads();            // everyone done reading operand stages

    float* sC = reinterpret_cast<float*>(smem);                 // 128 x CSTRIDE
    float2* sH = reinterpret_cast<float2*>(smem + BM * CSTRIDE * 4); // 128 x float2

    const int g = lane >> 2;
    const int tg = lane & 3;
    #pragma unroll
    for (int mt = 0; mt < 2; mt++) {
        #pragma unroll
        for (int nt = 0; nt < 8; nt++) {
            const int cl = wn * 64 + nt * 8 + tg * 2;
            #pragma unroll
            for (int rh = 0; rh < 2; rh++) {
                const int rl = wm * 32 + mt * 16 + g + rh * 8;
                *reinterpret_cast<float2*>(&sC[rl * CSTRIDE + cl]) =
                    make_float2(acc[mt][nt][rh * 2 + 0], acc[mt][nt][rh * 2 + 1]);
            }
        }
    }
    if (tid < BM) sH[tid] = g_h2a[row0 + tid];
    __syncthreads();

    // ---- coalesced epilogue: thread owns one fixed column ----
    const int coll = tid & 127;
    const int hi = tid >> 7;            // 0 or 1
    const int c = col0 + coll;
    const bool colok = c < V;
    const float2 vb = colok ? g_v2b[c] : make_float2(0.f, 1.f);

    #pragma unroll 4
    for (int it = 0; it < 64; it++) {
        const int rl = it * 2 + hi;
        const float2 ha = sH[rl];
        const float d = sC[rl * CSTRIDE + coll];

        float sq = fmaxf(fmaf(-2.0f, d, ha.x + vb.x), 0.0f);
        float t = fmaxf(sq * ha.y * vb.y, 1e-7f);
        float su;
        asm("sqrt.approx.f32 %0, %1;" : "=f"(su) : "f"(t * (t + 2.0f)));
        float lg;
        asm("lg2.approx.f32 %0, %1;" : "=f"(lg) : "f"(1.0f + t + su));
        const float o = lg * (-0.6931471805599453f);

        if (colok) stcs1(&out[(size_t)(row0 + rl) * V + c], o);
    }
}

// ---------------------------------------------------------------------------
extern "C" void kernel_launch(void* const* d_in, const int* in_sizes, int n_in,
                              void* d_out, int out_size) {
    const float* hs = (const float*)d_in[0];   // hidden_states [N, 256]
    const float* ve = (const float*)d_in[1];   // vocab_embeddings [V, 256]
    const int N = in_sizes[0] / DD;            // 4096
    const int V = in_sizes[1] / DD;            // 50257

    proj_kernel<true><<<(N + 7) / 8, 256>>>(hs, N);
    proj_kernel<false><<<(V + 7) / 8, 256>>>(ve, V);

    static int smem_set = 0;
    if (!smem_set) {
        cudaFuncSetAttribute(hyp_gemm_kernel,
                             cudaFuncAttributeMaxDynamicSharedMemorySize, SMEM_TOTAL);
        smem_set = 1;
    }
    dim3 grid((V + BN - 1) / BN, (N + BM - 1) / BM);
    hyp_gemm_kernel<<<grid, 256, SMEM_TOTAL>>>((float*)d_out, N, V);
}

// round 8
// speedup vs baseline: 6.1055x; 1.0808x over previous
#include <cuda_runtime.h>
#include <cuda_bf16.h>
#include <math.h>
#include <stdint.h>

#define DD 256
#define MAXN 4096
#define MAXV 50432
#define MAX_NORM (1.0f - 1e-5f)
#define EPSF 1e-7f

#define BM 128
#define BN 128
#define BK 64
#define SSTRIDE 72          // bf16 per smem row (64 + 8 pad) -> conflict-free ldmatrix

#define STAGE_BYTES (BM * SSTRIDE * 2)        // 18432 B per operand per stage
#define NSTAGE 3
#define CSTRIDE 132                            // fp32 epilogue tile stride
#define SMEM_TOTAL (2 * NSTAGE * STAGE_BYTES) // 110592 B (2 CTAs/SM: 221184 <= 228KB)

// ---- scratch (__device__ globals: allocation-free rule) ----
static __device__ __nv_bfloat16 g_hb[(size_t)MAXN * DD];
static __device__ __nv_bfloat16 g_vb[(size_t)MAXV * DD];
static __device__ float2 g_h2a[MAXN];   // (h2, 2/(1-h2))
static __device__ float2 g_v2b[MAXV];   // (v2, 1/(1-v2))

// ---------------- PTX helpers ----------------
__device__ __forceinline__ uint32_t smem_u32(const void* p) {
    return (uint32_t)__cvta_generic_to_shared(p);
}
__device__ __forceinline__ void cp16(uint32_t dst, const void* src, bool pred) {
    asm volatile("cp.async.cg.shared.global [%0], [%1], 16, %2;"
                 :: "r"(dst), "l"(src), "r"(pred ? 16u : 0u) : "memory");
}
__device__ __forceinline__ void cp_commit() {
    asm volatile("cp.async.commit_group;" ::: "memory");
}
template <int NN>
__device__ __forceinline__ void cp_wait() {
    asm volatile("cp.async.wait_group %0;" :: "n"(NN) : "memory");
}
__device__ __forceinline__ void ldsm_x4(uint32_t* r, uint32_t addr) {
    asm volatile("ldmatrix.sync.aligned.m8n8.x4.shared.b16 {%0,%1,%2,%3}, [%4];"
                 : "=r"(r[0]), "=r"(r[1]), "=r"(r[2]), "=r"(r[3]) : "r"(addr));
}
__device__ __forceinline__ void mma16816(float* c, const uint32_t* a,
                                         uint32_t b0, uint32_t b1) {
    asm volatile(
        "mma.sync.aligned.m16n8k16.row.col.f32.bf16.bf16.f32 "
        "{%0,%1,%2,%3}, {%4,%5,%6,%7}, {%8,%9}, {%0,%1,%2,%3};"
        : "+f"(c[0]), "+f"(c[1]), "+f"(c[2]), "+f"(c[3])
        : "r"(a[0]), "r"(a[1]), "r"(a[2]), "r"(a[3]), "r"(b0), "r"(b1));
}
__device__ __forceinline__ void stcs1(float* p, float x) {
    asm volatile("st.global.cs.f32 [%0], %1;" :: "l"(p), "f"(x) : "memory");
}
// ---- packed f32x2 (Blackwell base ISA) ----
__device__ __forceinline__ uint64_t pk2(float lo, float hi) {
    uint64_t r; asm("mov.b64 %0, {%1, %2};" : "=l"(r) : "f"(lo), "f"(hi)); return r;
}
__device__ __forceinline__ void upk2(float& lo, float& hi, uint64_t v) {
    asm("mov.b64 {%0, %1}, %2;" : "=f"(lo), "=f"(hi) : "l"(v));
}
__device__ __forceinline__ uint64_t add2(uint64_t a, uint64_t b) {
    uint64_t r; asm("add.rn.f32x2 %0, %1, %2;" : "=l"(r) : "l"(a), "l"(b)); return r;
}
__device__ __forceinline__ uint64_t mul2(uint64_t a, uint64_t b) {
    uint64_t r; asm("mul.rn.f32x2 %0, %1, %2;" : "=l"(r) : "l"(a), "l"(b)); return r;
}
__device__ __forceinline__ uint64_t fma2p(uint64_t a, uint64_t b, uint64_t c) {
    uint64_t r; asm("fma.rn.f32x2 %0, %1, %2, %3;" : "=l"(r) : "l"(a), "l"(b), "l"(c));
    return r;
}

// ---------------------------------------------------------------------------
// Projection: warp-per-row. Writes bf16 operand + per-row (n2, recip terms).
// ---------------------------------------------------------------------------
template <bool IS_H>
__global__ void proj_kernel(const float* __restrict__ in, int rows) {
    const int row = blockIdx.x * 8 + (threadIdx.x >> 5);
    const int lane = threadIdx.x & 31;
    if (row >= rows) return;

    const float4* p = reinterpret_cast<const float4*>(in) + (size_t)row * (DD / 4) + lane * 2;
    float4 x0 = p[0], x1 = p[1];
    float s = x0.x * x0.x + x0.y * x0.y + x0.z * x0.z + x0.w * x0.w +
              x1.x * x1.x + x1.y * x1.y + x1.z * x1.z + x1.w * x1.w;
    #pragma unroll
    for (int o = 16; o > 0; o >>= 1) s += __shfl_xor_sync(0xffffffffu, s, o);

    const float norm = sqrtf(s);
    const float scale = (norm > MAX_NORM) ? (MAX_NORM / fmaxf(norm, EPSF)) : 1.0f;
    const float n2 = s * scale * scale;

    __nv_bfloat16 ob[8];
    ob[0] = __float2bfloat16(x0.x * scale); ob[1] = __float2bfloat16(x0.y * scale);
    ob[2] = __float2bfloat16(x0.z * scale); ob[3] = __float2bfloat16(x0.w * scale);
    ob[4] = __float2bfloat16(x1.x * scale); ob[5] = __float2bfloat16(x1.y * scale);
    ob[6] = __float2bfloat16(x1.z * scale); ob[7] = __float2bfloat16(x1.w * scale);

    __nv_bfloat16* dst = (IS_H ? g_hb : g_vb) + (size_t)row * DD + lane * 8;
    *reinterpret_cast<uint4*>(dst) = *reinterpret_cast<const uint4*>(ob);

    if (lane == 0) {
        if (IS_H) g_h2a[row] = make_float2(n2, 2.0f / (1.0f - n2));
        else      g_v2b[row] = make_float2(n2, 1.0f / (1.0f - n2));
    }
}

// ---------------------------------------------------------------------------
// mma.sync bf16 GEMM (128x128 tile, BK=64, 3-stage cp.async pipeline) with
// smem-staged coalesced epilogue: packed f32x2 math + poly arccosh (1 MUFU).
// ---------------------------------------------------------------------------
__global__ void __launch_bounds__(256, 2)
hyp_gemm_kernel(float* __restrict__ out, int N, int V) {
    extern __shared__ __align__(16) char smem[];
    const uint32_t sA0 = smem_u32(smem);
    const uint32_t sB0 = sA0 + NSTAGE * STAGE_BYTES;

    const int tid = threadIdx.x;
    const int wid = tid >> 5;
    const int lane = tid & 31;
    const int wm = wid & 3;
    const int wn = wid >> 2;
    const int row0 = blockIdx.y * BM;
    const int col0 = blockIdx.x * BN;

    float acc[2][8][4];
    #pragma unroll
    for (int i = 0; i < 2; i++)
        #pragma unroll
        for (int j = 0; j < 8; j++)
            #pragma unroll
            for (int q = 0; q < 4; q++) acc[i][j][q] = 0.f;

    const int cr = tid >> 3;            // 0..31, x4 iters -> 128 rows
    const int cc = tid & 7;             // 16B column 0..7

    auto prefetch = [&](int stage, int k0) {
        #pragma unroll
        for (int i = 0; i < 4; i++) {
            const int r = cr + i * 32;
            const uint32_t so = (uint32_t)(r * SSTRIDE + cc * 8) * 2;
            cp16(sA0 + stage * STAGE_BYTES + so,
                 &g_hb[(size_t)(row0 + r) * DD + k0 + cc * 8], true);
            const int vr = col0 + r;
            const bool ok = vr < V;
            cp16(sB0 + stage * STAGE_BYTES + so,
                 &g_vb[(size_t)(ok ? vr : 0) * DD + k0 + cc * 8], ok);
        }
        cp_commit();
    };

    prefetch(0, 0);
    prefetch(1, BK);

    const int aRowBase = wm * 32 + (lane & 15);
    const int aColSel  = (lane >> 4) * 8;
    const int bRowBase = wn * 64 + (lane & 7) + ((lane >> 4) << 3);
    const int bColSel  = ((lane >> 3) & 1) * 8;

    #pragma unroll 1
    for (int ks = 0; ks < 4; ks++) {
        if (ks == 3) cp_wait<0>(); else cp_wait<1>();
        __syncthreads();
        if (ks < 2) prefetch((ks + 2) % NSTAGE, (ks + 2) * BK);

        const int stage = ks % NSTAGE;
        const uint32_t aBase = sA0 + stage * STAGE_BYTES;
        const uint32_t bBase = sB0 + stage * STAGE_BYTES;

        #pragma unroll
        for (int kp = 0; kp < 4; kp++) {
            uint32_t a[2][4];
            #pragma unroll
            for (int mt = 0; mt < 2; mt++) {
                const uint32_t ad = aBase +
                    (uint32_t)((aRowBase + mt * 16) * SSTRIDE + kp * 16 + aColSel) * 2;
                ldsm_x4(a[mt], ad);
            }
            uint32_t b[4][4];
            #pragma unroll
            for (int np = 0; np < 4; np++) {
                const uint32_t bd = bBase +
                    (uint32_t)((bRowBase + np * 16) * SSTRIDE + kp * 16 + bColSel) * 2;
                ldsm_x4(b[np], bd);
            }
            #pragma unroll
            for (int mt = 0; mt < 2; mt++)
                #pragma unroll
                for (int nt = 0; nt < 8; nt++)
                    mma16816(acc[mt][nt], a[mt],
                             b[nt >> 1][(nt & 1) * 2], b[nt >> 1][(nt & 1) * 2 + 1]);
        }
    }

    // ---- stage accumulators (and h2a) into smem ----
    __syncthreads();            // everyone done reading operand stages

    float* sC = reinterpret_cast<float*>(smem);                      // 128 x CSTRIDE
    float2* sH = reinterpret_cast<float2*>(smem + BM * CSTRIDE * 4); // 128 x float2

    const int g = lane >> 2;
    const int tg = lane & 3;
    #pragma unroll
    for (int mt = 0; mt < 2; mt++) {
        #pragma unroll
        for (int nt = 0; nt < 8; nt++) {
            const int cl = wn * 64 + nt * 8 + tg * 2;
            #pragma unroll
            for (int rh = 0; rh < 2; rh++) {
                const int rl = wm * 32 + mt * 16 + g + rh * 8;
                *reinterpret_cast<float2*>(&sC[rl * CSTRIDE + cl]) =
                    make_float2(acc[mt][nt][rh * 2 + 0], acc[mt][nt][rh * 2 + 1]);
            }
        }
    }
    if (tid < BM) sH[tid] = g_h2a[row0 + tid];
    __syncthreads();

    // ---- coalesced packed epilogue: thread owns one column, 2 rows/iter ----
    const int coll = tid & 127;
    const int hi = tid >> 7;            // 0 or 1
    const int c = col0 + coll;
    const bool colok = c < V;
    const float2 vb = colok ? g_v2b[c] : make_float2(0.f, 1.f);

    const uint64_t VBX2 = pk2(vb.x, vb.x);
    const uint64_t VBY2 = pk2(vb.y, vb.y);
    const uint64_t NEG2 = pk2(-2.0f, -2.0f);
    // -arccosh(1+t) = sqrt(2t) * (-P(t)); Taylor coeffs of -P, Horner order:
    const uint64_t C0 = pk2(-1.0f, -1.0f);
    const uint64_t C1 = pk2(1.0f / 12.0f, 1.0f / 12.0f);
    const uint64_t C2 = pk2(-3.0f / 160.0f, -3.0f / 160.0f);
    const uint64_t C3 = pk2(5.0f / 896.0f, 5.0f / 896.0f);
    const uint64_t C4 = pk2(-35.0f / 18432.0f, -35.0f / 18432.0f);
    const uint64_t C5 = pk2(63.0f / 90112.0f, 63.0f / 90112.0f);

    #pragma unroll 4
    for (int it = 0; it < 32; it++) {
        const int rl0 = it * 4 + hi * 2;
        const int rl1 = rl0 + 1;
        const float2 ha0 = sH[rl0];
        const float2 ha1 = sH[rl1];
        const float d0 = sC[rl0 * CSTRIDE + coll];
        const float d1 = sC[rl1 * CSTRIDE + coll];

        uint64_t D2 = pk2(d0, d1);
        uint64_t H2 = pk2(ha0.x, ha1.x);
        uint64_t A2 = pk2(ha0.y, ha1.y);

        uint64_t sq2 = fma2p(NEG2, D2, add2(H2, VBX2));   // h2+v2-2d
        uint64_t t2 = mul2(sq2, mul2(A2, VBY2));          // 2 sq / denom

        float t0, t1;
        upk2(t0, t1, t2);
        t0 = fmaxf(t0, 1e-7f);
        t1 = fmaxf(t1, 1e-7f);
        t2 = pk2(t0, t1);

        uint64_t p = fma2p(C5, t2, C4);
        p = fma2p(p, t2, C3);
        p = fma2p(p, t2, C2);
        p = fma2p(p, t2, C1);
        p = fma2p(p, t2, C0);                              // -P(t)

        float s0, s1;
        asm("sqrt.approx.f32 %0, %1;" : "=f"(s0) : "f"(t0 + t0));
        asm("sqrt.approx.f32 %0, %1;" : "=f"(s1) : "f"(t1 + t1));

        uint64_t O2 = mul2(pk2(s0, s1), p);                // -dist
        float o0, o1;
        upk2(o0, o1, O2);

        if (colok) {
            stcs1(&out[(size_t)(row0 + rl0) * V + c], o0);
            stcs1(&out[(size_t)(row0 + rl1) * V + c], o1);
        }
    }
}

// ---------------------------------------------------------------------------
extern "C" void kernel_launch(void* const* d_in, const int* in_sizes, int n_in,
                              void* d_out, int out_size) {
    const float* hs = (const float*)d_in[0];   // hidden_states [N, 256]
    const float* ve = (const float*)d_in[1];   // vocab_embeddings [V, 256]
    const int N = in_sizes[0] / DD;            // 4096
    const int V = in_sizes[1] / DD;            // 50257

    proj_kernel<true><<<(N + 7) / 8, 256>>>(hs, N);
    proj_kernel<false><<<(V + 7) / 8, 256>>>(ve, V);

    static int smem_set = 0;
    if (!smem_set) {
        cudaFuncSetAttribute(hyp_gemm_kernel,
                             cudaFuncAttributeMaxDynamicSharedMemorySize, SMEM_TOTAL);
        smem_set = 1;
    }
    dim3 grid((V + BN - 1) / BN, (N + BM - 1) / BM);
    hyp_gemm_kernel<<<grid, 256, SMEM_TOTAL>>>((float*)d_out, N, V);
}